// round 5
// baseline (speedup 1.0000x reference)
#include <cuda_runtime.h>
#include <math.h>

#define Nn 30000
#define Ee 480000
#define Hh 128
#define NHh 4
#define Gg 64
#define EPSf 1e-5f

// ---------------- scratch (device globals: no allocation allowed) ----------------
__device__ float g_src[Nn*Hh];
__device__ float g_dst[Nn*Hh];
__device__ float g_val[Nn*Hh];
__device__ float g_tmp1[(size_t)Ee*Hh];
__device__ float g_scores[(size_t)Ee*NHh];
__device__ float g_smax[Nn*NHh];
__device__ float g_den[Nn*NHh];
__device__ float g_numer[Nn*Hh];     // later reused as agg
__device__ float g_nodenew[Nn*Hh];
__device__ float g_gate[Nn*Hh];
__device__ float g_h1[Nn*Hh];
__device__ float g_n1[Nn*Hh];
__device__ float g_t1[Nn*Hh];
__device__ float g_fx[Nn*Hh];
__device__ float g_h2[Nn*Hh];
__device__ float g_Wg1[Hh*Hh];
__device__ float g_Wg2[Hh*Hh];
// layout: [0,G*H) sum1 | [G*H,2G*H) sq1 | [2G*H,3G*H) sum2 | [3G*H,4G*H) sq2 | [4G*H,4G*H+G) cnt
__device__ float g_stats[4*Gg*Hh + Gg];

// ---------------- generic 128-wide fp32 GEMM: C = act(A[M,128]@B[128,128] + bias (+C)) ----
// act: 0 none, 1 leaky(0.01), 2 sigmoid.  accum: add previous C before act.
__global__ void gemm128(const float* __restrict__ A, const float* __restrict__ B,
                        const float* __restrict__ bias, float* __restrict__ C,
                        int M, int act, int accum) {
    extern __shared__ float sm[];
    float* Bs = sm;           // 128*128
    float* As = sm + 16384;   // 64 rows * 132 (padded)
    float4* Bs4 = (float4*)Bs;
    float4* As4 = (float4*)As;
    const float4* B4 = (const float4*)B;
    const float4* A4 = (const float4*)A;
    int tid = threadIdx.x;
#pragma unroll
    for (int it = 0; it < 16; it++) Bs4[tid + 256*it] = B4[tid + 256*it];
    int row0 = blockIdx.x * 64;
#pragma unroll
    for (int it = 0; it < 8; it++) {
        int v = tid + 256*it;
        int r = v >> 5, kc = v & 31;
        float4 z = make_float4(0.f,0.f,0.f,0.f);
        As4[r*33 + kc] = (row0 + r < M) ? A4[(size_t)(row0 + r)*32 + kc] : z;
    }
    __syncthreads();
    int rg = tid >> 5, cg = tid & 31;
    float4 acc[8];
#pragma unroll
    for (int rr = 0; rr < 8; rr++) acc[rr] = make_float4(0.f,0.f,0.f,0.f);
#pragma unroll 2
    for (int k4 = 0; k4 < 32; k4++) {
        float4 bv0 = Bs4[(4*k4+0)*32 + cg];
        float4 bv1 = Bs4[(4*k4+1)*32 + cg];
        float4 bv2 = Bs4[(4*k4+2)*32 + cg];
        float4 bv3 = Bs4[(4*k4+3)*32 + cg];
#pragma unroll
        for (int rr = 0; rr < 8; rr++) {
            float4 a4 = As4[(rg*8+rr)*33 + k4];
            acc[rr].x += a4.x*bv0.x + a4.y*bv1.x + a4.z*bv2.x + a4.w*bv3.x;
            acc[rr].y += a4.x*bv0.y + a4.y*bv1.y + a4.z*bv2.y + a4.w*bv3.y;
            acc[rr].z += a4.x*bv0.z + a4.y*bv1.z + a4.z*bv2.z + a4.w*bv3.z;
            acc[rr].w += a4.x*bv0.w + a4.y*bv1.w + a4.z*bv2.w + a4.w*bv3.w;
        }
    }
    float4 bi = make_float4(0.f,0.f,0.f,0.f);
    if (bias) bi = ((const float4*)bias)[cg];
#pragma unroll
    for (int rr = 0; rr < 8; rr++) {
        int r = row0 + rg*8 + rr;
        if (r < M) {
            float4 v = acc[rr];
            v.x += bi.x; v.y += bi.y; v.z += bi.z; v.w += bi.w;
            if (accum) {
                float4 co = ((float4*)C)[(size_t)r*32 + cg];
                v.x += co.x; v.y += co.y; v.z += co.z; v.w += co.w;
            }
            if (act == 1) {
                v.x = v.x > 0.f ? v.x : 0.01f*v.x;
                v.y = v.y > 0.f ? v.y : 0.01f*v.y;
                v.z = v.z > 0.f ? v.z : 0.01f*v.z;
                v.w = v.w > 0.f ? v.w : 0.01f*v.w;
            } else if (act == 2) {
                v.x = 1.f/(1.f+expf(-v.x));
                v.y = 1.f/(1.f+expf(-v.y));
                v.z = 1.f/(1.f+expf(-v.z));
                v.w = 1.f/(1.f+expf(-v.w));
            }
            ((float4*)C)[(size_t)r*32 + cg] = v;
        }
    }
}

// ---------------- edge MLP stage 1: tmp1 = leaky([edge,dist] @ We1 + be1) ----------------
__global__ void edge_pre(const float* __restrict__ edge, const float* __restrict__ coords,
                         const int* __restrict__ ei, const float* __restrict__ We1,
                         const float* __restrict__ be1) {
    __shared__ float We1s[17*128];
    __shared__ float be1s[128];
    int tid = threadIdx.x;
    for (int v = tid; v < 17*128; v += 256) We1s[v] = We1[v];
    if (tid < 128) be1s[tid] = be1[tid];
    __syncthreads();
    int w = tid >> 5, lane = tid & 31;
    int e = blockIdx.x * 8 + w;
    if (e >= Ee) return;
    int i = ei[e], j = ei[Ee + e];
    float dx = coords[3*i+0] - coords[3*j+0];
    float dy = coords[3*i+1] - coords[3*j+1];
    float dz = coords[3*i+2] - coords[3*j+2];
    float dist = sqrtf(dx*dx + dy*dy + dz*dz + 1e-12f) * 0.1f;
    float xv = dist;
    if (lane < 16) xv = edge[(size_t)e*16 + lane];
    float4 acc = ((const float4*)be1s)[lane];
    const float4* W4 = (const float4*)We1s;
#pragma unroll
    for (int t = 0; t < 17; t++) {
        float xt = __shfl_sync(0xffffffffu, xv, t);
        float4 w4 = W4[t*32 + lane];
        acc.x += xt*w4.x; acc.y += xt*w4.y; acc.z += xt*w4.z; acc.w += xt*w4.w;
    }
    acc.x = acc.x > 0.f ? acc.x : 0.01f*acc.x;
    acc.y = acc.y > 0.f ? acc.y : 0.01f*acc.y;
    acc.z = acc.z > 0.f ? acc.z : 0.01f*acc.z;
    acc.w = acc.w > 0.f ? acc.w : 0.01f*acc.w;
    ((float4*)g_tmp1)[(size_t)e*32 + lane] = acc;
}

// ---------------- edge main: e = tmp1@We2+be2; edge_result; scores; smax; edge_new -------
__global__ void edge_main(const float* __restrict__ We2, const float* __restrict__ be2,
                          const float* __restrict__ Wue, const float* __restrict__ bue,
                          const int* __restrict__ ei, float* __restrict__ out_edge) {
    extern __shared__ float sm[];
    float* Bs = sm;                  // 16384  We2
    float* As = Bs + 16384;          // 8448   tmp1 tile / er tile (64 x 132)
    float* Ws = As + 8448;           // 2048   Wue
    float* score_s = Ws + 2048;      // 256
    float* be2s = score_s + 256;     // 128
    float* bues = be2s + 128;        // 16
    int*   is_ = (int*)(bues + 16);  // 64
    int*   js_ = is_ + 64;           // 64
    int tid = threadIdx.x;
    int e0 = blockIdx.x * 64;
    float4* Bs4 = (float4*)Bs;
    float4* As4 = (float4*)As;
    float4* Ws4 = (float4*)Ws;
    const float4* We24 = (const float4*)We2;
    const float4* Wue4 = (const float4*)Wue;
#pragma unroll
    for (int it = 0; it < 16; it++) Bs4[tid + 256*it] = We24[tid + 256*it];
    Ws4[tid] = Wue4[tid];
    Ws4[tid + 256] = Wue4[tid + 256];
    if (tid < 128) be2s[tid] = be2[tid];
    if (tid < 16) bues[tid] = bue[tid];
    score_s[tid] = 0.f;
    if (tid < 64) {
        int e = e0 + tid;
        is_[tid] = (e < Ee) ? ei[e] : 0;
        js_[tid] = (e < Ee) ? ei[Ee + e] : 0;
    }
    const float4* T4 = (const float4*)g_tmp1;
#pragma unroll
    for (int it = 0; it < 8; it++) {
        int v = tid + 256*it;
        int r = v >> 5, kc = v & 31;
        int e = e0 + r;
        As4[r*33 + kc] = (e < Ee) ? T4[(size_t)e*32 + kc] : make_float4(0.f,0.f,0.f,0.f);
    }
    __syncthreads();
    int rg = tid >> 5, cg = tid & 31;
    float4 bi = ((float4*)be2s)[cg];
    float4 acc[8];
#pragma unroll
    for (int rr = 0; rr < 8; rr++) acc[rr] = bi;
#pragma unroll 2
    for (int k4 = 0; k4 < 32; k4++) {
        float4 bv0 = Bs4[(4*k4+0)*32 + cg];
        float4 bv1 = Bs4[(4*k4+1)*32 + cg];
        float4 bv2 = Bs4[(4*k4+2)*32 + cg];
        float4 bv3 = Bs4[(4*k4+3)*32 + cg];
#pragma unroll
        for (int rr = 0; rr < 8; rr++) {
            float4 a4 = As4[(rg*8+rr)*33 + k4];
            acc[rr].x += a4.x*bv0.x + a4.y*bv1.x + a4.z*bv2.x + a4.w*bv3.x;
            acc[rr].y += a4.x*bv0.y + a4.y*bv1.y + a4.z*bv2.y + a4.w*bv3.y;
            acc[rr].z += a4.x*bv0.z + a4.y*bv1.z + a4.z*bv2.z + a4.w*bv3.z;
            acc[rr].w += a4.x*bv0.w + a4.y*bv1.w + a4.z*bv2.w + a4.w*bv3.w;
        }
    }
    __syncthreads();   // done reading tmp1 tile; safe to overwrite with er
    const float inv = 0.17677669529663688f;  // 1/sqrt(32)
    const float4* S4 = (const float4*)g_src;
    const float4* D4 = (const float4*)g_dst;
#pragma unroll
    for (int rr = 0; rr < 8; rr++) {
        int r = rg*8 + rr;
        int e = e0 + r;
        if (e < Ee) {
            int i = is_[r], j = js_[r];
            float4 s4 = S4[(size_t)j*32 + cg];
            float4 d4 = D4[(size_t)i*32 + cg];
            float4 er;
            er.x = d4.x * s4.x * acc[rr].x * inv;
            er.y = d4.y * s4.y * acc[rr].y * inv;
            er.z = d4.z * s4.z * acc[rr].z * inv;
            er.w = d4.w * s4.w * acc[rr].w * inv;
            float sp = fabsf(er.x) + fabsf(er.y) + fabsf(er.z) + fabsf(er.w);
            atomicAdd(&score_s[r*4 + (cg >> 3)], sp);
            As4[r*33 + cg] = er;
        }
    }
    __syncthreads();
    // write scores + atomicMax into smax (scores >= 0, so int compare on float bits is exact)
    {
        int r = tid >> 2, h = tid & 3;
        int e = e0 + r;
        if (e < Ee) {
            float s = score_s[r*4 + h];
            g_scores[(size_t)e*4 + h] = s;
            atomicMax((int*)&g_smax[is_[r]*4 + h], __float_as_int(s));
        }
    }
    // edge_new = er @ Wue + bue  -> out_edge [E,16]
    {
        int r = tid >> 2, c4 = tid & 3;
        int e = e0 + r;
        if (e < Ee) {
            float4 a = ((float4*)bues)[c4];
#pragma unroll 4
            for (int k = 0; k < 128; k++) {
                float av = As[r*132 + k];
                float4 w4 = Ws4[k*4 + c4];
                a.x += av*w4.x; a.y += av*w4.y; a.z += av*w4.z; a.w += av*w4.w;
            }
            ((float4*)out_edge)[(size_t)e*4 + c4] = a;
        }
    }
}

// ---------------- pass 2: exp weights, den, weighted value aggregation ----------------
__global__ void edge_attn(const int* __restrict__ ei) {
    int w = threadIdx.x >> 5, lane = threadIdx.x & 31;
    int e = blockIdx.x * 8 + w;
    if (e >= Ee) return;
    int i = ei[e], j = ei[Ee + e];
    float ex = 0.f;
    if (lane < 4) {
        float s = g_scores[(size_t)e*4 + lane];
        float m = g_smax[i*4 + lane];
        ex = expf(s - m);
        atomicAdd(&g_den[i*4 + lane], ex);
    }
    float exh = __shfl_sync(0xffffffffu, ex, lane >> 3);
    float4 v4 = ((const float4*)g_val)[(size_t)j*32 + lane];
    float* base = &g_numer[(size_t)i*128 + lane*4];
    atomicAdd(base + 0, exh*v4.x);
    atomicAdd(base + 1, exh*v4.y);
    atomicAdd(base + 2, exh*v4.z);
    atomicAdd(base + 3, exh*v4.w);
}

// ---------------- elementwise kernels ----------------
__global__ void k_agg() {
    int idx = blockIdx.x*256 + threadIdx.x;
    if (idx >= Nn*Hh) return;
    int n = idx >> 7, c = idx & 127;
    float den = g_den[n*4 + (c >> 5)];
    float v = g_numer[idx];
    g_numer[idx] = (den > 0.f) ? v/den : 0.f;
}

__global__ void k_prepw(const float* __restrict__ Wg) {
    int idx = blockIdx.x*256 + threadIdx.x;
    if (idx >= Hh*Hh) return;
    g_Wg1[idx] = Wg[idx] + Wg[idx + 2*Hh*Hh];
    g_Wg2[idx] = Wg[idx + Hh*Hh] - Wg[idx + 2*Hh*Hh];
}

__global__ void k_h1(const float* __restrict__ node, const int* __restrict__ batch) {
    int idx = blockIdx.x*256 + threadIdx.x;
    if (idx >= Nn*Hh) return;
    int n = idx >> 7, c = idx & 127;
    float g = g_gate[idx];
    float x = g * g_nodenew[idx] + node[idx];
    g_h1[idx] = x;
    int b = batch[n];
    atomicAdd(&g_stats[b*Hh + c], x);
    atomicAdd(&g_stats[Gg*Hh + b*Hh + c], x*x);
    if (c == 0) atomicAdd(&g_stats[4*Gg*Hh + b], 1.f);
}

__global__ void k_h2(const int* __restrict__ batch) {
    int idx = blockIdx.x*256 + threadIdx.x;
    if (idx >= Nn*Hh) return;
    int n = idx >> 7, c = idx & 127;
    float x = g_gate[idx] * g_fx[idx] + g_n1[idx];
    g_h2[idx] = x;
    int b = batch[n];
    atomicAdd(&g_stats[2*Gg*Hh + b*Hh + c], x);
    atomicAdd(&g_stats[3*Gg*Hh + b*Hh + c], x*x);
}

// GraphNorm: out = w*(x - a*mean)*rsqrt(var+eps) + b;  var = E[x^2] + mean^2*(a^2 - 2a)
__global__ void k_norm(const float* __restrict__ w_, const float* __restrict__ b_,
                       const float* __restrict__ a_, const int* __restrict__ batch,
                       const float* __restrict__ X, float* __restrict__ Y, int statoff) {
    int idx = blockIdx.x*256 + threadIdx.x;
    if (idx >= Nn*Hh) return;
    int n = idx >> 7, c = idx & 127;
    int b = batch[n];
    float cnt = fmaxf(g_stats[4*Gg*Hh + b], 1.f);
    float mean = g_stats[statoff + b*Hh + c] / cnt;
    float s2   = g_stats[statoff + Gg*Hh + b*Hh + c] / cnt;
    float a = a_[c];
    float var = s2 + mean*mean*(a*a - 2.f*a);
    float x = X[idx];
    Y[idx] = w_[c] * (x - a*mean) * rsqrtf(var + EPSf) + b_[c];
}

// ---------------- launch ----------------
extern "C" void kernel_launch(void* const* d_in, const int* in_sizes, int n_in,
                              void* d_out, int out_size) {
    const float* node = (const float*)d_in[0];
    const float* edge = (const float*)d_in[1];
    const float* coords = (const float*)d_in[2];
    const float* Ws = (const float*)d_in[3];  const float* bs = (const float*)d_in[4];
    const float* Wd = (const float*)d_in[5];  const float* bd = (const float*)d_in[6];
    const float* Wv = (const float*)d_in[7];  const float* bv = (const float*)d_in[8];
    const float* We1 = (const float*)d_in[9]; const float* be1 = (const float*)d_in[10];
    const float* We2 = (const float*)d_in[11];const float* be2 = (const float*)d_in[12];
    const float* Wun = (const float*)d_in[13];const float* bun = (const float*)d_in[14];
    const float* Wue = (const float*)d_in[15];const float* bue = (const float*)d_in[16];
    const float* Wg  = (const float*)d_in[17];const float* bg  = (const float*)d_in[18];
    const float* Wf1 = (const float*)d_in[19];const float* bf1 = (const float*)d_in[20];
    const float* Wf2 = (const float*)d_in[21];const float* bf2 = (const float*)d_in[22];
    const float* gn1w = (const float*)d_in[23];
    const float* gn1b = (const float*)d_in[24];
    const float* gn1a = (const float*)d_in[25];
    const float* gn2w = (const float*)d_in[26];
    const float* gn2b = (const float*)d_in[27];
    const float* gn2a = (const float*)d_in[28];
    const int* ei = (const int*)d_in[29];
    const int* batch = (const int*)d_in[30];

    float* out = (float*)d_out;
    float* out_n2 = out;
    float* out_edge = out + (size_t)Nn*Hh;
    float* out_coords = out + (size_t)Nn*Hh + (size_t)Ee*16;

    size_t gemm_smem = (16384 + 64*132) * sizeof(float);   // 99328
    size_t em_smem   = (16384 + 8448 + 2048 + 256 + 128 + 16 + 128) * sizeof(float); // 109632
    cudaFuncSetAttribute(gemm128, cudaFuncAttributeMaxDynamicSharedMemorySize, (int)gemm_smem);
    cudaFuncSetAttribute(edge_main, cudaFuncAttributeMaxDynamicSharedMemorySize, (int)em_smem);

    // scratch pointers
    float *p_src,*p_dst,*p_val,*p_numer,*p_nodenew,*p_gate,*p_h1,*p_n1,*p_t1,*p_fx,*p_h2,*p_wg1,*p_wg2;
    void* p;
    cudaGetSymbolAddress(&p, g_src); p_src = (float*)p;
    cudaGetSymbolAddress(&p, g_dst); p_dst = (float*)p;
    cudaGetSymbolAddress(&p, g_val); p_val = (float*)p;
    cudaGetSymbolAddress(&p, g_numer); p_numer = (float*)p;
    cudaGetSymbolAddress(&p, g_nodenew); p_nodenew = (float*)p;
    cudaGetSymbolAddress(&p, g_gate); p_gate = (float*)p;
    cudaGetSymbolAddress(&p, g_h1); p_h1 = (float*)p;
    cudaGetSymbolAddress(&p, g_n1); p_n1 = (float*)p;
    cudaGetSymbolAddress(&p, g_t1); p_t1 = (float*)p;
    cudaGetSymbolAddress(&p, g_fx); p_fx = (float*)p;
    cudaGetSymbolAddress(&p, g_h2); p_h2 = (float*)p;
    cudaGetSymbolAddress(&p, g_Wg1); p_wg1 = (float*)p;
    cudaGetSymbolAddress(&p, g_Wg2); p_wg2 = (float*)p;

    // zero scratch that receives atomics
    cudaGetSymbolAddress(&p, g_smax);  cudaMemsetAsync(p, 0, sizeof(float)*Nn*NHh, 0);
    cudaGetSymbolAddress(&p, g_den);   cudaMemsetAsync(p, 0, sizeof(float)*Nn*NHh, 0);
    cudaGetSymbolAddress(&p, g_numer); cudaMemsetAsync(p, 0, sizeof(float)*Nn*Hh, 0);
    cudaGetSymbolAddress(&p, g_stats); cudaMemsetAsync(p, 0, sizeof(float)*(4*Gg*Hh + Gg), 0);

    int gemmGrid = (Nn + 63) / 64;          // 469
    int elemGrid = (Nn*Hh + 255) / 256;     // 15000
    int edgeWGrid = Ee / 8;                 // 60000 (warp per edge)
    int edgeMGrid = Ee / 64;                // 7500

    // node projections
    gemm128<<<gemmGrid, 256, gemm_smem>>>(node, Ws, bs, p_src, Nn, 0, 0);
    gemm128<<<gemmGrid, 256, gemm_smem>>>(node, Wd, bd, p_dst, Nn, 0, 0);
    gemm128<<<gemmGrid, 256, gemm_smem>>>(node, Wv, bv, p_val, Nn, 0, 0);

    // edge MLP stage 1
    edge_pre<<<edgeWGrid, 256>>>(edge, coords, ei, We1, be1);

    // edge main (GEMM2, edge_result, scores, smax, edge_new)
    edge_main<<<edgeMGrid, 256, em_smem>>>(We2, be2, Wue, bue, ei, out_edge);

    // softmax + aggregation
    edge_attn<<<edgeWGrid, 256>>>(ei);
    k_agg<<<elemGrid, 256>>>();

    // node_new = agg @ Wun + bun
    gemm128<<<gemmGrid, 256, gemm_smem>>>(p_numer, Wun, bun, p_nodenew, Nn, 0, 0);

    // gate = sigmoid(node_new@Wg1 + node@Wg2 + bg)
    k_prepw<<<(Hh*Hh + 255)/256, 256>>>(Wg);
    gemm128<<<gemmGrid, 256, gemm_smem>>>(p_nodenew, p_wg1, (const float*)0, p_gate, Nn, 0, 0);
    gemm128<<<gemmGrid, 256, gemm_smem>>>(node, p_wg2, bg, p_gate, Nn, 2, 1);

    // h1 = g*node_new + node; stats1
    k_h1<<<elemGrid, 256>>>(node, batch);
    k_norm<<<elemGrid, 256>>>(gn1w, gn1b, gn1a, batch, p_h1, p_n1, 0);

    // fix_node
    gemm128<<<gemmGrid, 256, gemm_smem>>>(p_n1, Wf1, bf1, p_t1, Nn, 1, 0);
    gemm128<<<gemmGrid, 256, gemm_smem>>>(p_t1, Wf2, bf2, p_fx, Nn, 0, 0);

    // h2 = g*fx + n1; stats2; norm2 -> output
    k_h2<<<elemGrid, 256>>>(batch);
    k_norm<<<elemGrid, 256>>>(gn2w, gn2b, gn2a, batch, p_h2, out_n2, 2*Gg*Hh);

    // coords pass-through
    cudaMemcpyAsync(out_coords, coords, sizeof(float)*Nn*3, cudaMemcpyDeviceToDevice, 0);

    (void)in_sizes; (void)n_in; (void)out_size;
}

// round 7
// speedup vs baseline: 1.2752x; 1.2752x over previous
#include <cuda_runtime.h>
#include <math.h>

#define Nn 30000
#define Ee 480000
#define Hh 128
#define NHh 4
#define Gg 64
#define EPSf 1e-5f

typedef unsigned long long ull;
union U2 { float4 f; struct { ull lo, hi; } u; };

__device__ __forceinline__ ull pk2(float x, float y) {
    ull r; asm("mov.b64 %0,{%1,%2};" : "=l"(r) : "f"(x), "f"(y)); return r;
}
__device__ __forceinline__ ull f2(ull a, ull b, ull c) {
    ull d; asm("fma.rn.f32x2 %0,%1,%2,%3;" : "=l"(d) : "l"(a), "l"(b), "l"(c)); return d;
}
__device__ __forceinline__ float2 up2(ull v) {
    float2 f; asm("mov.b64 {%0,%1},%2;" : "=f"(f.x), "=f"(f.y) : "l"(v)); return f;
}

// ---------------- scratch (device globals) ----------------
__device__ float g_src[Nn*Hh];
__device__ float g_dst[Nn*Hh];
__device__ float g_val[Nn*Hh];
__device__ float g_scores[(size_t)Ee*NHh];
__device__ float g_smax[Nn*NHh];
__device__ float g_den[Nn*NHh];
__device__ float g_numer[Nn*Hh];
__device__ float g_nodenew[Nn*Hh];
__device__ float g_gate[Nn*Hh];
__device__ float g_h1[Nn*Hh];
__device__ float g_n1[Nn*Hh];
__device__ float g_t1[Nn*Hh];
__device__ float g_fx[Nn*Hh];
__device__ float g_h2[Nn*Hh];
__device__ float g_Wg1[Hh*Hh];
__device__ float g_Wg2[Hh*Hh];
__device__ float g_stats[4*Gg*Hh + Gg];

// ============ node GEMM: C = act(A[M,128]@B[128,128] + bias (+C)) ============
// 128-row tile, 256 threads, 8x8 per thread, f32x2 FMA, de-interleaved B in smem.
__global__ __launch_bounds__(256) void gemm128x(
        const float* __restrict__ A, const float* __restrict__ B,
        const float* __restrict__ bias, float* __restrict__ C,
        int M, int act, int accum) {
    extern __shared__ float sm[];
    float* Bs = sm;           // 16384 floats (de-interleaved 16B chunks)
    float* As = sm + 16384;   // 128 x 132
    float4* Bs4 = (float4*)Bs;
    float4* As4 = (float4*)As;
    const float4* B4 = (const float4*)B;
    const float4* A4 = (const float4*)A;
    int tid = threadIdx.x;
    int row0 = blockIdx.x * 128;

    // load B permuted: chunk c4 -> (c4&1)*16 + (c4>>1)
#pragma unroll
    for (int it = 0; it < 16; it++) {
        int v = tid + 256*it;
        int c4 = v & 31;
        Bs4[(v & ~31) | (((c4 & 1) << 4) | (c4 >> 1))] = B4[v];
    }
#pragma unroll
    for (int it = 0; it < 16; it++) {
        int v = tid + 256*it;
        int r = v >> 5, q = v & 31;
        As4[r*33 + q] = (row0 + r < M) ? A4[(size_t)(row0 + r)*32 + q]
                                       : make_float4(0.f,0.f,0.f,0.f);
    }
    __syncthreads();

    int rg = tid >> 4, cg = tid & 15;
    int r0 = rg * 8;
    ull acc[8][4];
#pragma unroll
    for (int rr = 0; rr < 8; rr++) {
        acc[rr][0] = 0ull; acc[rr][1] = 0ull; acc[rr][2] = 0ull; acc[rr][3] = 0ull;
    }
    for (int k4 = 0; k4 < 32; k4++) {
        float4 a4[8];
#pragma unroll
        for (int rr = 0; rr < 8; rr++) a4[rr] = As4[(r0 + rr)*33 + k4];
#pragma unroll
        for (int kk = 0; kk < 4; kk++) {
            U2 w0, w1;
            w0.f = Bs4[(k4*4 + kk)*32 + cg];
            w1.f = Bs4[(k4*4 + kk)*32 + 16 + cg];
#pragma unroll
            for (int rr = 0; rr < 8; rr++) {
                float a = ((float*)&a4[rr])[kk];
                ull pa = pk2(a, a);
                acc[rr][0] = f2(pa, w0.u.lo, acc[rr][0]);
                acc[rr][1] = f2(pa, w0.u.hi, acc[rr][1]);
                acc[rr][2] = f2(pa, w1.u.lo, acc[rr][2]);
                acc[rr][3] = f2(pa, w1.u.hi, acc[rr][3]);
            }
        }
    }
    float4 bi0 = make_float4(0.f,0.f,0.f,0.f), bi1 = bi0;
    if (bias) {
        bi0 = ((const float4*)bias)[cg*2];
        bi1 = ((const float4*)bias)[cg*2 + 1];
    }
#pragma unroll
    for (int rr = 0; rr < 8; rr++) {
        int r = row0 + r0 + rr;
        if (r < M) {
            float2 f0 = up2(acc[rr][0]), f1 = up2(acc[rr][1]);
            float2 f2_ = up2(acc[rr][2]), f3 = up2(acc[rr][3]);
            float4 v0 = make_float4(f0.x + bi0.x, f0.y + bi0.y, f1.x + bi0.z, f1.y + bi0.w);
            float4 v1 = make_float4(f2_.x + bi1.x, f2_.y + bi1.y, f3.x + bi1.z, f3.y + bi1.w);
            if (accum) {
                float4 c0 = ((float4*)C)[(size_t)r*32 + cg*2];
                float4 c1 = ((float4*)C)[(size_t)r*32 + cg*2 + 1];
                v0.x += c0.x; v0.y += c0.y; v0.z += c0.z; v0.w += c0.w;
                v1.x += c1.x; v1.y += c1.y; v1.z += c1.z; v1.w += c1.w;
            }
            if (act == 1) {
                v0.x = v0.x > 0.f ? v0.x : 0.01f*v0.x;  v0.y = v0.y > 0.f ? v0.y : 0.01f*v0.y;
                v0.z = v0.z > 0.f ? v0.z : 0.01f*v0.z;  v0.w = v0.w > 0.f ? v0.w : 0.01f*v0.w;
                v1.x = v1.x > 0.f ? v1.x : 0.01f*v1.x;  v1.y = v1.y > 0.f ? v1.y : 0.01f*v1.y;
                v1.z = v1.z > 0.f ? v1.z : 0.01f*v1.z;  v1.w = v1.w > 0.f ? v1.w : 0.01f*v1.w;
            } else if (act == 2) {
                v0.x = 1.f/(1.f+expf(-v0.x)); v0.y = 1.f/(1.f+expf(-v0.y));
                v0.z = 1.f/(1.f+expf(-v0.z)); v0.w = 1.f/(1.f+expf(-v0.w));
                v1.x = 1.f/(1.f+expf(-v1.x)); v1.y = 1.f/(1.f+expf(-v1.y));
                v1.z = 1.f/(1.f+expf(-v1.z)); v1.w = 1.f/(1.f+expf(-v1.w));
            }
            ((float4*)C)[(size_t)r*32 + cg*2]     = v0;
            ((float4*)C)[(size_t)r*32 + cg*2 + 1] = v1;
        }
    }
}

// ============ fused edge kernel ============
// stage1 MLP + GEMM2 + edge_result + scores/smax + edge_new, 128 edges/block.
__global__ __launch_bounds__(256) void edge_fused(
        const float* __restrict__ edge, const float* __restrict__ coords,
        const float* __restrict__ We1, const float* __restrict__ be1,
        const float* __restrict__ We2, const float* __restrict__ be2,
        const float* __restrict__ Wue, const float* __restrict__ bue,
        const int* __restrict__ ei, float* __restrict__ out_edge) {
    extern __shared__ float sm[];
    float* Bs      = sm;                 // 16384  (We1 then We2 de-interleaved)
    float* As      = Bs + 16384;         // 128*132 = 16896 (tmp then er)
    float* xs      = As + 16896;         // 128*20 = 2560
    float* Ws      = xs + 2560;          // 2048 (Wue)
    float* score_s = Ws + 2048;          // 512
    float* be1s    = score_s + 512;      // 128
    float* be2s    = be1s + 128;         // 128
    float* bues    = be2s + 128;         // 16
    int*   is_     = (int*)(bues + 16);  // 128
    int*   js_     = is_ + 128;          // 128

    int tid = threadIdx.x;
    int e0 = blockIdx.x * 128;
    float4* Bs4 = (float4*)Bs;
    float4* As4 = (float4*)As;
    float4* xs4 = (float4*)xs;
    float4* Ws4 = (float4*)Ws;

    if (tid < 128) { is_[tid] = ei[e0 + tid]; js_[tid] = ei[Ee + e0 + tid]; }
    for (int v = tid; v < 17*128; v += 256) Bs[v] = We1[v];
    if (tid < 128) { be1s[tid] = be1[tid]; be2s[tid] = be2[tid]; }
    if (tid < 16) bues[tid] = bue[tid];
    score_s[tid] = 0.f; score_s[tid + 256] = 0.f;
    Ws4[tid]       = ((const float4*)Wue)[tid];
    Ws4[tid + 256] = ((const float4*)Wue)[tid + 256];
    {
        const float4* E4 = (const float4*)edge;
#pragma unroll
        for (int it = 0; it < 2; it++) {
            int v = tid + 256*it;
            int r = v >> 2, q = v & 3;
            xs4[r*5 + q] = E4[(size_t)(e0 + r)*4 + q];
        }
    }
    __syncthreads();
    if (tid < 128) {
        int i = is_[tid], j = js_[tid];
        float dx = coords[3*i]   - coords[3*j];
        float dy = coords[3*i+1] - coords[3*j+1];
        float dz = coords[3*i+2] - coords[3*j+2];
        xs[tid*20 + 16] = sqrtf(dx*dx + dy*dy + dz*dz + 1e-12f) * 0.1f;
    }
    __syncthreads();

    int rg = tid >> 4, cg = tid & 15;
    int r0 = rg * 8;

    // ---- stage 1: tmp = leaky([edge,dist] @ We1 + be1) into As ----
    {
        ull acc1[8][4];
        float4 b0 = ((float4*)be1s)[cg*2], b1 = ((float4*)be1s)[cg*2 + 1];
        ull i0 = pk2(b0.x,b0.y), i1 = pk2(b0.z,b0.w), i2 = pk2(b1.x,b1.y), i3 = pk2(b1.z,b1.w);
#pragma unroll
        for (int rr = 0; rr < 8; rr++) { acc1[rr][0]=i0; acc1[rr][1]=i1; acc1[rr][2]=i2; acc1[rr][3]=i3; }
#pragma unroll
        for (int k = 0; k < 17; k++) {
            U2 w0, w1;
            w0.f = Bs4[k*32 + cg*2];
            w1.f = Bs4[k*32 + cg*2 + 1];
#pragma unroll
            for (int rr = 0; rr < 8; rr++) {
                float a = xs[(r0 + rr)*20 + k];
                ull pa = pk2(a, a);
                acc1[rr][0] = f2(pa, w0.u.lo, acc1[rr][0]);
                acc1[rr][1] = f2(pa, w0.u.hi, acc1[rr][1]);
                acc1[rr][2] = f2(pa, w1.u.lo, acc1[rr][2]);
                acc1[rr][3] = f2(pa, w1.u.hi, acc1[rr][3]);
            }
        }
#pragma unroll
        for (int rr = 0; rr < 8; rr++) {
            float2 f0 = up2(acc1[rr][0]), f1 = up2(acc1[rr][1]);
            float2 f2_ = up2(acc1[rr][2]), f3 = up2(acc1[rr][3]);
            float v[8] = { f0.x, f0.y, f1.x, f1.y, f2_.x, f2_.y, f3.x, f3.y };
#pragma unroll
            for (int q = 0; q < 8; q++) v[q] = v[q] > 0.f ? v[q] : 0.01f*v[q];
            As4[(r0 + rr)*33 + cg*2]     = make_float4(v[0], v[1], v[2], v[3]);
            As4[(r0 + rr)*33 + cg*2 + 1] = make_float4(v[4], v[5], v[6], v[7]);
        }
    }
    __syncthreads();

    // ---- load We2 de-interleaved ----
    {
        const float4* W24 = (const float4*)We2;
#pragma unroll
        for (int it = 0; it < 16; it++) {
            int v = tid + 256*it;
            int c4 = v & 31;
            Bs4[(v & ~31) | (((c4 & 1) << 4) | (c4 >> 1))] = W24[v];
        }
    }
    __syncthreads();

    // ---- GEMM2: e = tmp @ We2 + be2 ----
    ull acc[8][4];
    {
        float4 b0 = ((float4*)be2s)[cg*2], b1 = ((float4*)be2s)[cg*2 + 1];
        ull i0 = pk2(b0.x,b0.y), i1 = pk2(b0.z,b0.w), i2 = pk2(b1.x,b1.y), i3 = pk2(b1.z,b1.w);
#pragma unroll
        for (int rr = 0; rr < 8; rr++) { acc[rr][0]=i0; acc[rr][1]=i1; acc[rr][2]=i2; acc[rr][3]=i3; }
    }
    for (int k4 = 0; k4 < 32; k4++) {
        float4 a4[8];
#pragma unroll
        for (int rr = 0; rr < 8; rr++) a4[rr] = As4[(r0 + rr)*33 + k4];
#pragma unroll
        for (int kk = 0; kk < 4; kk++) {
            U2 w0, w1;
            w0.f = Bs4[(k4*4 + kk)*32 + cg];
            w1.f = Bs4[(k4*4 + kk)*32 + 16 + cg];
#pragma unroll
            for (int rr = 0; rr < 8; rr++) {
                float a = ((float*)&a4[rr])[kk];
                ull pa = pk2(a, a);
                acc[rr][0] = f2(pa, w0.u.lo, acc[rr][0]);
                acc[rr][1] = f2(pa, w0.u.hi, acc[rr][1]);
                acc[rr][2] = f2(pa, w1.u.lo, acc[rr][2]);
                acc[rr][3] = f2(pa, w1.u.hi, acc[rr][3]);
            }
        }
    }
    __syncthreads();   // all reads of tmp done; As will hold er

    // ---- edge_result + scores ----
    {
        const float inv = 0.17677669529663688f;  // 1/sqrt(32)
        const float4* S4 = (const float4*)g_src;
        const float4* D4 = (const float4*)g_dst;
        int h = cg >> 2;
#pragma unroll
        for (int rr = 0; rr < 8; rr++) {
            int r = r0 + rr;
            int i = is_[r], j = js_[r];
            float4 sA = S4[(size_t)j*32 + cg*2], sB = S4[(size_t)j*32 + cg*2 + 1];
            float4 dA = D4[(size_t)i*32 + cg*2], dB = D4[(size_t)i*32 + cg*2 + 1];
            float2 f0 = up2(acc[rr][0]), f1 = up2(acc[rr][1]);
            float2 f2_ = up2(acc[rr][2]), f3 = up2(acc[rr][3]);
            float e_[8];
            e_[0] = dA.x*sA.x*f0.x*inv;  e_[1] = dA.y*sA.y*f0.y*inv;
            e_[2] = dA.z*sA.z*f1.x*inv;  e_[3] = dA.w*sA.w*f1.y*inv;
            e_[4] = dB.x*sB.x*f2_.x*inv; e_[5] = dB.y*sB.y*f2_.y*inv;
            e_[6] = dB.z*sB.z*f3.x*inv;  e_[7] = dB.w*sB.w*f3.y*inv;
            float sp = fabsf(e_[0]) + fabsf(e_[1]) + fabsf(e_[2]) + fabsf(e_[3])
                     + fabsf(e_[4]) + fabsf(e_[5]) + fabsf(e_[6]) + fabsf(e_[7]);
            atomicAdd(&score_s[r*4 + h], sp);
            As4[r*33 + cg*2]     = make_float4(e_[0], e_[1], e_[2], e_[3]);
            As4[r*33 + cg*2 + 1] = make_float4(e_[4], e_[5], e_[6], e_[7]);
        }
    }
    __syncthreads();

    // ---- scores out + smax atomicMax ----
#pragma unroll
    for (int t = 0; t < 2; t++) {
        int v = tid + 256*t;
        int r = v >> 2, h = v & 3;
        float s = score_s[v];
        g_scores[(size_t)(e0 + r)*4 + h] = s;
        atomicMax((int*)&g_smax[is_[r]*4 + h], __float_as_int(s));
    }

    // ---- edge_new = er @ Wue + bue ----
    {
        int r = tid >> 1, cp = tid & 1;
        ull acc2[4];
        float4 bb0 = ((float4*)bues)[cp*2], bb1 = ((float4*)bues)[cp*2 + 1];
        acc2[0] = pk2(bb0.x, bb0.y); acc2[1] = pk2(bb0.z, bb0.w);
        acc2[2] = pk2(bb1.x, bb1.y); acc2[3] = pk2(bb1.z, bb1.w);
#pragma unroll 4
        for (int k = 0; k < 128; k++) {
            float a = As[r*132 + k];
            ull pa = pk2(a, a);
            U2 w0, w1;
            w0.f = Ws4[k*4 + cp*2];
            w1.f = Ws4[k*4 + cp*2 + 1];
            acc2[0] = f2(pa, w0.u.lo, acc2[0]);
            acc2[1] = f2(pa, w0.u.hi, acc2[1]);
            acc2[2] = f2(pa, w1.u.lo, acc2[2]);
            acc2[3] = f2(pa, w1.u.hi, acc2[3]);
        }
        float2 r0_ = up2(acc2[0]), r1_ = up2(acc2[1]), r2_ = up2(acc2[2]), r3_ = up2(acc2[3]);
        ((float4*)out_edge)[(size_t)(e0 + r)*4 + cp*2]     = make_float4(r0_.x, r0_.y, r1_.x, r1_.y);
        ((float4*)out_edge)[(size_t)(e0 + r)*4 + cp*2 + 1] = make_float4(r2_.x, r2_.y, r3_.x, r3_.y);
    }
}

// ============ pass 2: exp weights, den, weighted value aggregation ============
__global__ void edge_attn(const int* __restrict__ ei) {
    int w = threadIdx.x >> 5, lane = threadIdx.x & 31;
    int e = blockIdx.x * 8 + w;
    int i = ei[e], j = ei[Ee + e];
    float ex = 0.f;
    if (lane < 4) {
        float s = g_scores[(size_t)e*4 + lane];
        float m = g_smax[i*4 + lane];
        ex = expf(s - m);
        atomicAdd(&g_den[i*4 + lane], ex);
    }
    float exh = __shfl_sync(0xffffffffu, ex, lane >> 3);
    float4 v4 = ((const float4*)g_val)[(size_t)j*32 + lane];
    float* base = &g_numer[(size_t)i*128 + lane*4];
    asm volatile("red.global.add.v4.f32 [%0], {%1,%2,%3,%4};"
                 :: "l"(base), "f"(exh*v4.x), "f"(exh*v4.y), "f"(exh*v4.z), "f"(exh*v4.w)
                 : "memory");
}

// ---------------- elementwise kernels ----------------
__global__ void k_agg() {
    int idx = blockIdx.x*256 + threadIdx.x;
    if (idx >= Nn*Hh) return;
    int n = idx >> 7, c = idx & 127;
    float den = g_den[n*4 + (c >> 5)];
    float v = g_numer[idx];
    g_numer[idx] = (den > 0.f) ? v/den : 0.f;
}

__global__ void k_prepw(const float* __restrict__ Wg) {
    int idx = blockIdx.x*256 + threadIdx.x;
    if (idx >= Hh*Hh) return;
    g_Wg1[idx] = Wg[idx] + Wg[idx + 2*Hh*Hh];
    g_Wg2[idx] = Wg[idx + Hh*Hh] - Wg[idx + 2*Hh*Hh];
}

__global__ void k_h1(const float* __restrict__ node, const int* __restrict__ batch) {
    int idx = blockIdx.x*256 + threadIdx.x;
    if (idx >= Nn*Hh) return;
    int n = idx >> 7, c = idx & 127;
    float g = g_gate[idx];
    float x = g * g_nodenew[idx] + node[idx];
    g_h1[idx] = x;
    int b = batch[n];
    atomicAdd(&g_stats[b*Hh + c], x);
    atomicAdd(&g_stats[Gg*Hh + b*Hh + c], x*x);
    if (c == 0) atomicAdd(&g_stats[4*Gg*Hh + b], 1.f);
}

__global__ void k_h2(const int* __restrict__ batch) {
    int idx = blockIdx.x*256 + threadIdx.x;
    if (idx >= Nn*Hh) return;
    int n = idx >> 7, c = idx & 127;
    float x = g_gate[idx] * g_fx[idx] + g_n1[idx];
    g_h2[idx] = x;
    int b = batch[n];
    atomicAdd(&g_stats[2*Gg*Hh + b*Hh + c], x);
    atomicAdd(&g_stats[3*Gg*Hh + b*Hh + c], x*x);
}

__global__ void k_norm(const float* __restrict__ w_, const float* __restrict__ b_,
                       const float* __restrict__ a_, const int* __restrict__ batch,
                       const float* __restrict__ X, float* __restrict__ Y, int statoff) {
    int idx = blockIdx.x*256 + threadIdx.x;
    if (idx >= Nn*Hh) return;
    int n = idx >> 7, c = idx & 127;
    int b = batch[n];
    float cnt = fmaxf(g_stats[4*Gg*Hh + b], 1.f);
    float mean = g_stats[statoff + b*Hh + c] / cnt;
    float s2   = g_stats[statoff + Gg*Hh + b*Hh + c] / cnt;
    float a = a_[c];
    float var = s2 + mean*mean*(a*a - 2.f*a);
    float x = X[idx];
    Y[idx] = w_[c] * (x - a*mean) * rsqrtf(var + EPSf) + b_[c];
}

// ---------------- launch ----------------
extern "C" void kernel_launch(void* const* d_in, const int* in_sizes, int n_in,
                              void* d_out, int out_size) {
    const float* node = (const float*)d_in[0];
    const float* edge = (const float*)d_in[1];
    const float* coords = (const float*)d_in[2];
    const float* Ws = (const float*)d_in[3];  const float* bs = (const float*)d_in[4];
    const float* Wd = (const float*)d_in[5];  const float* bd = (const float*)d_in[6];
    const float* Wv = (const float*)d_in[7];  const float* bv = (const float*)d_in[8];
    const float* We1 = (const float*)d_in[9]; const float* be1 = (const float*)d_in[10];
    const float* We2 = (const float*)d_in[11];const float* be2 = (const float*)d_in[12];
    const float* Wun = (const float*)d_in[13];const float* bun = (const float*)d_in[14];
    const float* Wue = (const float*)d_in[15];const float* bue = (const float*)d_in[16];
    const float* Wg  = (const float*)d_in[17];const float* bg  = (const float*)d_in[18];
    const float* Wf1 = (const float*)d_in[19];const float* bf1 = (const float*)d_in[20];
    const float* Wf2 = (const float*)d_in[21];const float* bf2 = (const float*)d_in[22];
    const float* gn1w = (const float*)d_in[23];
    const float* gn1b = (const float*)d_in[24];
    const float* gn1a = (const float*)d_in[25];
    const float* gn2w = (const float*)d_in[26];
    const float* gn2b = (const float*)d_in[27];
    const float* gn2a = (const float*)d_in[28];
    const int* ei = (const int*)d_in[29];
    const int* batch = (const int*)d_in[30];

    float* out = (float*)d_out;
    float* out_n2 = out;
    float* out_edge = out + (size_t)Nn*Hh;
    float* out_coords = out + (size_t)Nn*Hh + (size_t)Ee*16;

    size_t gemm_smem = (16384 + 128*132) * sizeof(float);                 // 133120
    size_t ef_smem   = (16384 + 16896 + 2560 + 2048 + 512 + 128 + 128 + 16) * sizeof(float)
                     + 256 * sizeof(int);                                  // 155712
    cudaFuncSetAttribute(gemm128x, cudaFuncAttributeMaxDynamicSharedMemorySize, (int)gemm_smem);
    cudaFuncSetAttribute(edge_fused, cudaFuncAttributeMaxDynamicSharedMemorySize, (int)ef_smem);

    float *p_src,*p_dst,*p_val,*p_numer,*p_nodenew,*p_gate,*p_h1,*p_n1,*p_t1,*p_fx,*p_h2,*p_wg1,*p_wg2;
    void* p;
    cudaGetSymbolAddress(&p, g_src); p_src = (float*)p;
    cudaGetSymbolAddress(&p, g_dst); p_dst = (float*)p;
    cudaGetSymbolAddress(&p, g_val); p_val = (float*)p;
    cudaGetSymbolAddress(&p, g_numer); p_numer = (float*)p;
    cudaGetSymbolAddress(&p, g_nodenew); p_nodenew = (float*)p;
    cudaGetSymbolAddress(&p, g_gate); p_gate = (float*)p;
    cudaGetSymbolAddress(&p, g_h1); p_h1 = (float*)p;
    cudaGetSymbolAddress(&p, g_n1); p_n1 = (float*)p;
    cudaGetSymbolAddress(&p, g_t1); p_t1 = (float*)p;
    cudaGetSymbolAddress(&p, g_fx); p_fx = (float*)p;
    cudaGetSymbolAddress(&p, g_h2); p_h2 = (float*)p;
    cudaGetSymbolAddress(&p, g_Wg1); p_wg1 = (float*)p;
    cudaGetSymbolAddress(&p, g_Wg2); p_wg2 = (float*)p;

    cudaGetSymbolAddress(&p, g_smax);  cudaMemsetAsync(p, 0, sizeof(float)*Nn*NHh, 0);
    cudaGetSymbolAddress(&p, g_den);   cudaMemsetAsync(p, 0, sizeof(float)*Nn*NHh, 0);
    cudaGetSymbolAddress(&p, g_numer); cudaMemsetAsync(p, 0, sizeof(float)*Nn*Hh, 0);
    cudaGetSymbolAddress(&p, g_stats); cudaMemsetAsync(p, 0, sizeof(float)*(4*Gg*Hh + Gg), 0);

    int gemmGrid = (Nn + 127) / 128;        // 235
    int elemGrid = (Nn*Hh + 255) / 256;     // 15000
    int edgeWGrid = Ee / 8;                 // 60000
    int edgeFGrid = Ee / 128;               // 3750 (exact)

    // node projections
    gemm128x<<<gemmGrid, 256, gemm_smem>>>(node, Ws, bs, p_src, Nn, 0, 0);
    gemm128x<<<gemmGrid, 256, gemm_smem>>>(node, Wd, bd, p_dst, Nn, 0, 0);
    gemm128x<<<gemmGrid, 256, gemm_smem>>>(node, Wv, bv, p_val, Nn, 0, 0);

    // fused edge pipeline
    edge_fused<<<edgeFGrid, 256, ef_smem>>>(edge, coords, We1, be1, We2, be2,
                                            Wue, bue, ei, out_edge);

    // softmax + aggregation
    edge_attn<<<edgeWGrid, 256>>>(ei);
    k_agg<<<elemGrid, 256>>>();

    // node_new = agg @ Wun + bun
    gemm128x<<<gemmGrid, 256, gemm_smem>>>(p_numer, Wun, bun, p_nodenew, Nn, 0, 0);

    // gate = sigmoid(node_new@Wg1 + node@Wg2 + bg)
    k_prepw<<<(Hh*Hh + 255)/256, 256>>>(Wg);
    gemm128x<<<gemmGrid, 256, gemm_smem>>>(p_nodenew, p_wg1, (const float*)0, p_gate, Nn, 0, 0);
    gemm128x<<<gemmGrid, 256, gemm_smem>>>(node, p_wg2, bg, p_gate, Nn, 2, 1);

    // h1 = g*node_new + node; stats1; norm1
    k_h1<<<elemGrid, 256>>>(node, batch);
    k_norm<<<elemGrid, 256>>>(gn1w, gn1b, gn1a, batch, p_h1, p_n1, 0);

    // fix_node
    gemm128x<<<gemmGrid, 256, gemm_smem>>>(p_n1, Wf1, bf1, p_t1, Nn, 1, 0);
    gemm128x<<<gemmGrid, 256, gemm_smem>>>(p_t1, Wf2, bf2, p_fx, Nn, 0, 0);

    // h2 = g*fx + n1; stats2; norm2 -> output
    k_h2<<<elemGrid, 256>>>(batch);
    k_norm<<<elemGrid, 256>>>(gn2w, gn2b, gn2a, batch, p_h2, out_n2, 2*Gg*Hh);

    // coords pass-through
    cudaMemcpyAsync(out_coords, coords, sizeof(float)*Nn*3, cudaMemcpyDeviceToDevice, 0);

    (void)in_sizes; (void)n_in; (void)out_size;
}